// round 6
// baseline (speedup 1.0000x reference)
#include <cuda_runtime.h>
#include <math.h>
#include <stdint.h>

typedef unsigned long long ull;

// ---------------- scratch (device globals; no allocations allowed) ----------------
__device__ float g_qT  [1024 * 256];      // [b*128+r][e]   e = h*16+d
__device__ float g_kTT [8 * 256 * 128];   // [b][e][c]
__device__ float g_v1  [1024 * 256];      // [b][h][s][d]
__device__ float g_v2  [1024 * 256];      // [b][h][s][d]
__device__ float g_ms1 [2097152];         // [b][h][r][c]
__device__ float g_ms2 [2097152];         // [b][h][r][c]
__device__ float g_attn1[1024 * 256];     // [b*128+r][h*16+d]
__device__ float g_attn2[1024 * 256];     // [b*128+c][h*16+d]
__device__ float g_part[1024 * 4];        // per-block {s1,q1,s2,q2}
__device__ float g_stats[2];              // inv_std1, inv_std2
// frag-packed split weights: per fragment+lane: {bhi0, bhi1, blo0, blo1}
__device__ float4 gW1p[256 * 32];         // frag = nf*4+ks  (nf 0..63, ks 0..3)
__device__ float4 gW2p[256 * 32];         // frag = ks*4+nf  (ks 0..63, nf 0..3)

// ---------------- helpers ----------------
__device__ __forceinline__ float fast_tanh(float x) {
    return 1.f - 2.f / (__expf(2.f * x) + 1.f);
}
__device__ __forceinline__ float tf32f(float x) {
    uint32_t u; asm("cvt.rna.tf32.f32 %0, %1;" : "=r"(u) : "f"(x));
    return __uint_as_float(u);
}
__device__ __forceinline__ void mma_tf32(float* c,
                                         uint32_t a0, uint32_t a1, uint32_t a2, uint32_t a3,
                                         uint32_t b0, uint32_t b1) {
    asm volatile(
        "mma.sync.aligned.m16n8k8.row.col.f32.tf32.tf32.f32 "
        "{%0,%1,%2,%3}, {%4,%5,%6,%7}, {%8,%9}, {%0,%1,%2,%3};"
        : "+f"(c[0]), "+f"(c[1]), "+f"(c[2]), "+f"(c[3])
        : "r"(a0), "r"(a1), "r"(a2), "r"(a3), "r"(b0), "r"(b1));
}

__global__ void k_nop() {}

// ---------------- K0: pack W1/W2 into per-fragment hi/lo float4s ----------------
__global__ void k_prep(const float* __restrict__ w1, const float* __restrict__ w2) {
    int idx = blockIdx.x * 256 + threadIdx.x;   // 0..16383
    if (idx >= 16384) return;
    int sel  = idx >> 13;
    int f    = idx & 8191;
    int lane = f & 31;
    int frag = f >> 5;            // 0..255
    int g = lane >> 2, tig = lane & 3;
    float b0, b1;
    if (sel == 0) {
        int nf = frag >> 2, ks = frag & 3;
        b0 = w1[(ks * 8 + tig) * 512 + nf * 8 + g];
        b1 = w1[(ks * 8 + tig + 4) * 512 + nf * 8 + g];
    } else {
        int ks = frag >> 2, nf = frag & 3;
        b0 = w2[(ks * 8 + tig) * 32 + nf * 8 + g];
        b1 = w2[(ks * 8 + tig + 4) * 32 + nf * 8 + g];
    }
    float h0 = tf32f(b0), h1 = tf32f(b1);
    float l0 = tf32f(b0 - h0), l1 = tf32f(b1 - h1);
    float4 v = make_float4(h0, h1, l0, l1);
    if (sel == 0) gW1p[frag * 32 + lane] = v;
    else          gW2p[frag * 32 + lane] = v;
}

// ---------------- K1: qkv projection GEMM ----------------
#define SM_QKV ((32 * 260 + 256 * 64) * 4)
__global__ void k_qkv(const float* __restrict__ x1, const float* __restrict__ x2,
                      const float* __restrict__ W) {
    extern __shared__ float smq[];
    float* sA = smq;             // 32 x 260 (padded)
    float* sB = smq + 32 * 260;  // 256 x 64
    const int m0 = blockIdx.x * 32, n0 = blockIdx.y * 64;
    const bool isX1 = (m0 < 1024);
    const float* src = isX1 ? x1 : x2;
    const int mm = m0 & 1023;
    const int b = mm >> 7, s0 = mm & 127;
    const int tid = threadIdx.x;

    for (int idx = tid; idx < 2048; idx += 256) {
        int row = idx >> 6, kk = (idx & 63) << 2;
        float4 v = *(const float4*)(src + (b * 128 + s0 + row) * 256 + kk);
        *(float4*)(sA + row * 260 + kk) = v;
    }
    for (int idx = tid; idx < 4096; idx += 256) {
        int row = idx >> 4, c4 = (idx & 15) << 2;
        float4 v = *(const float4*)(W + row * 512 + n0 + c4);
        *(float4*)(sB + row * 64 + c4) = v;
    }
    __syncthreads();

    const int r = tid >> 3, cg = tid & 7;
    float acc[8];
#pragma unroll
    for (int j = 0; j < 8; j++) acc[j] = 0.f;
    const float4* sB4 = (const float4*)sB;
#pragma unroll 4
    for (int k = 0; k < 256; k++) {
        float a = sA[r * 260 + k];
        float4 b0 = sB4[k * 16 + cg * 2];
        float4 b1 = sB4[k * 16 + cg * 2 + 1];
        acc[0] += a * b0.x; acc[1] += a * b0.y; acc[2] += a * b0.z; acc[3] += a * b0.w;
        acc[4] += a * b1.x; acc[5] += a * b1.y; acc[6] += a * b1.z; acc[7] += a * b1.w;
    }

    const int s = s0 + r;
#pragma unroll
    for (int j = 0; j < 8; j++) {
        int n = n0 + cg * 8 + j;
        float v = acc[j];
        if (n < 256) {
            if (isX1) g_qT[(b * 128 + s) * 256 + n] = v;
            else      g_kTT[(b * 256 + n) * 128 + s] = v;
        } else {
            int h = (n - 256) >> 4, d = n & 15;
            float* dst = isX1 ? g_v1 : g_v2;
            dst[((b * 16 + h) * 128 + s) * 16 + d] = v;
        }
    }
}

// ---------------- K3: tensor-core fused dot + MixedScoreFF MLP ----------------
// grid 1024 = (b,r). 256 threads = 8 warps, warp w owns rows (c) [16w,16w+16).
// tf32x2 split: every product = Ahi*Bhi + Alo*Bhi + Ahi*Blo.
// Independent accumulators break MMA dependency chains (depth 4/8 instead of 12/24).
// smem (fp32, split done in registers at consume):
//   sH [128][68] 34816 B | sA [128][36] 18432 B | sq [256] 1024 B = 54272 B -> 4 CTA/SM
#define SM_MLP 54272
__global__ void __launch_bounds__(256, 4)
k_mlp(const float* __restrict__ cost) {
    extern __shared__ float smf[];
    float* sH = smf;                      // pitch 68
    float* sA = smf + 8704;               // pitch 36
    float* sq = smf + 8704 + 4608;

    const int blk = blockIdx.x;           // b*128 + r
    const int b = blk >> 7;
    const int tid = threadIdx.x;
    const int warp = tid >> 5, lane = tid & 31;
    const int g = lane >> 2, tig = lane & 3;

    // ---- phase 0: q row to smem; compute din; build A (fp32) ----
    sq[tid] = g_qT[(blk << 8) + tid];
    __syncthreads();

    {
        const int c = tid & 127, half = tid >> 7;   // half: h 0..7 vs 8..15
        float cv = cost[blk * 128 + c];
        const float* kb = g_kTT + b * 32768 + c;
#pragma unroll
        for (int hh = 0; hh < 8; hh++) {
            int h = half * 8 + hh;
            float a = 0.f;
#pragma unroll
            for (int d = 0; d < 16; d++)
                a += sq[h * 16 + d] * kb[(h * 16 + d) * 128];
            sA[c * 36 + 2 * h] = a * 0.25f;
            sA[c * 36 + 2 * h + 1] = cv;
        }
    }
    __syncthreads();

    // ---- load A fragments, split hi/lo in registers ----
    const int arow0 = warp * 16 + g, arow1 = arow0 + 8;
    uint32_t Ahi[4][4], Alo[4][4];
#pragma unroll
    for (int ks = 0; ks < 4; ks++) {
        float a0 = sA[arow0 * 36 + ks * 8 + tig];
        float a1 = sA[arow1 * 36 + ks * 8 + tig];
        float a2 = sA[arow0 * 36 + ks * 8 + tig + 4];
        float a3 = sA[arow1 * 36 + ks * 8 + tig + 4];
        float h0 = tf32f(a0), h1 = tf32f(a1), h2 = tf32f(a2), h3 = tf32f(a3);
        Ahi[ks][0] = __float_as_uint(h0); Alo[ks][0] = __float_as_uint(tf32f(a0 - h0));
        Ahi[ks][1] = __float_as_uint(h1); Alo[ks][1] = __float_as_uint(tf32f(a1 - h1));
        Ahi[ks][2] = __float_as_uint(h2); Alo[ks][2] = __float_as_uint(tf32f(a2 - h2));
        Ahi[ks][3] = __float_as_uint(h3); Alo[ks][3] = __float_as_uint(tf32f(a3 - h3));
    }

    float OUThh[4][4], OUTc[4][4];
#pragma unroll
    for (int i = 0; i < 4; i++)
#pragma unroll
        for (int j = 0; j < 4; j++) { OUThh[i][j] = 0.f; OUTc[i][j] = 0.f; }

    // ---- 8 chunks of 64 hidden units ----
    for (int chunk = 0; chunk < 8; chunk++) {
        // layer 1: H[16x64] for this warp's rows; 3 independent chains of depth 4
#pragma unroll
        for (int nfp = 0; nfp < 8; nfp++) {
            float hh[4] = {0.f, 0.f, 0.f, 0.f};
            float lh[4] = {0.f, 0.f, 0.f, 0.f};
            float hl[4] = {0.f, 0.f, 0.f, 0.f};
#pragma unroll
            for (int ks = 0; ks < 4; ks++) {
                float4 bw = gW1p[(((chunk * 8 + nfp) * 4 + ks) << 5) + lane];
                uint32_t bh0 = __float_as_uint(bw.x), bh1 = __float_as_uint(bw.y);
                uint32_t bl0 = __float_as_uint(bw.z), bl1 = __float_as_uint(bw.w);
                mma_tf32(hh, Ahi[ks][0], Ahi[ks][1], Ahi[ks][2], Ahi[ks][3], bh0, bh1);
                mma_tf32(lh, Alo[ks][0], Alo[ks][1], Alo[ks][2], Alo[ks][3], bh0, bh1);
                mma_tf32(hl, Ahi[ks][0], Ahi[ks][1], Ahi[ks][2], Ahi[ks][3], bl0, bl1);
            }
            float h0 = fmaxf(hh[0] + lh[0] + hl[0], 0.f);
            float h1 = fmaxf(hh[1] + lh[1] + hl[1], 0.f);
            float h2 = fmaxf(hh[2] + lh[2] + hl[2], 0.f);
            float h3 = fmaxf(hh[3] + lh[3] + hl[3], 0.f);
            int col = nfp * 8 + 2 * tig;
            sH[arow0 * 68 + col]     = h0;
            sH[arow0 * 68 + col + 1] = h1;
            sH[arow1 * 68 + col]     = h2;
            sH[arow1 * 68 + col + 1] = h3;
        }
        __syncwarp();
        // layer 2: OUT[16x32] += H[16x64] @ W2[64x32]; split H in registers
#pragma unroll
        for (int ksp = 0; ksp < 8; ksp++) {
            float f0 = sH[arow0 * 68 + ksp * 8 + tig];
            float f1 = sH[arow1 * 68 + ksp * 8 + tig];
            float f2 = sH[arow0 * 68 + ksp * 8 + tig + 4];
            float f3 = sH[arow1 * 68 + ksp * 8 + tig + 4];
            float t0 = tf32f(f0), t1 = tf32f(f1), t2 = tf32f(f2), t3 = tf32f(f3);
            uint32_t ah0 = __float_as_uint(t0), ah1 = __float_as_uint(t1);
            uint32_t ah2 = __float_as_uint(t2), ah3 = __float_as_uint(t3);
            uint32_t al0 = __float_as_uint(tf32f(f0 - t0)), al1 = __float_as_uint(tf32f(f1 - t1));
            uint32_t al2 = __float_as_uint(tf32f(f2 - t2)), al3 = __float_as_uint(tf32f(f3 - t3));
#pragma unroll
            for (int nf = 0; nf < 4; nf++) {
                float4 bw = gW2p[(((chunk * 8 + ksp) * 4 + nf) << 5) + lane];
                uint32_t bh0 = __float_as_uint(bw.x), bh1 = __float_as_uint(bw.y);
                uint32_t bl0 = __float_as_uint(bw.z), bl1 = __float_as_uint(bw.w);
                mma_tf32(OUThh[nf], ah0, ah1, ah2, ah3, bh0, bh1);
                mma_tf32(OUTc[nf],  al0, al1, al2, al3, bh0, bh1);
                mma_tf32(OUTc[nf],  ah0, ah1, ah2, ah3, bl0, bl1);
            }
        }
        __syncwarp();
    }

    // ---- write OUT to smem (reuse sH as [128][33]) then coalesced global write ----
    float* sO = sH;
    __syncthreads();   // everyone done with H before repurposing
#pragma unroll
    for (int nf = 0; nf < 4; nf++) {
        int col = nf * 8 + 2 * tig;
        sO[arow0 * 33 + col]     = OUThh[nf][0] + OUTc[nf][0];
        sO[arow0 * 33 + col + 1] = OUThh[nf][1] + OUTc[nf][1];
        sO[arow1 * 33 + col]     = OUThh[nf][2] + OUTc[nf][2];
        sO[arow1 * 33 + col + 1] = OUThh[nf][3] + OUTc[nf][3];
    }
    __syncthreads();

    const int r = blk & 127;
    float s1 = 0.f, q1 = 0.f, s2 = 0.f, q2 = 0.f;
    for (int i = tid; i < 2048; i += 256) {
        int h = i >> 7, cc = i & 127;
        float m1 = sO[cc * 33 + 2 * h];
        float m2 = sO[cc * 33 + 2 * h + 1];
        g_ms1[((b * 16 + h) * 128 + r) * 128 + cc] = m1;
        g_ms2[((b * 16 + h) * 128 + r) * 128 + cc] = m2;
        s1 += m1; q1 += m1 * m1; s2 += m2; q2 += m2 * m2;
    }

    float v[4] = {s1, q1, s2, q2};
#pragma unroll
    for (int i = 0; i < 4; i++)
        for (int off = 16; off; off >>= 1) v[i] += __shfl_xor_sync(0xffffffffu, v[i], off);
    __shared__ float red[4][8];
    if (lane == 0) { red[0][warp] = v[0]; red[1][warp] = v[1]; red[2][warp] = v[2]; red[3][warp] = v[3]; }
    __syncthreads();
    if (tid == 0) {
#pragma unroll
        for (int i = 0; i < 4; i++) {
            float s = 0.f;
#pragma unroll
            for (int j = 0; j < 8; j++) s += red[i][j];
            g_part[blk * 4 + i] = s;
        }
    }
}

// ---------------- K4: std reduction (ddof=1) ----------------
__global__ void k_std() {
    __shared__ double sh[4][128];
    const int tid = threadIdx.x;  // 128
    double a0 = 0, a1 = 0, a2 = 0, a3 = 0;
    for (int i = tid; i < 1024; i += 128) {
        const float* p = g_part + i * 4;
        a0 += p[0]; a1 += p[1]; a2 += p[2]; a3 += p[3];
    }
    sh[0][tid] = a0; sh[1][tid] = a1; sh[2][tid] = a2; sh[3][tid] = a3;
    __syncthreads();
    for (int o = 64; o; o >>= 1) {
        if (tid < o) {
#pragma unroll
            for (int i = 0; i < 4; i++) sh[i][tid] += sh[i][tid + o];
        }
        __syncthreads();
    }
    if (tid == 0) {
        const double N = 2097152.0;
        double v1 = (sh[1][0] - sh[0][0] * sh[0][0] / N) / (N - 1.0);
        double v2 = (sh[3][0] - sh[2][0] * sh[2][0] / N) / (N - 1.0);
        g_stats[0] = (float)(1.0 / sqrt(v1));
        g_stats[1] = (float)(1.0 / sqrt(v2));
    }
}

// ---------------- K5a: h1 attention (softmax over c), 2 blocks per plane ----------------
#define SM_AT1 ((64 * 128 + 128 * 16) * 4)
__global__ void k_attn1() {
    extern __shared__ float sma[];
    float* sl = sma;            // [64 r][128 c]
    float* sv = sma + 8192;     // v2 plane [128 c][16 d]
    const int blk = blockIdx.x;      // 256
    const int p = blk >> 1, rh = blk & 1;
    const int tid = threadIdx.x;     // 256
    const float inv = g_stats[0];
    const float* mp = g_ms1 + p * 16384 + rh * 8192;
    for (int idx = tid; idx < 8192; idx += 256) sl[idx] = 10.f * fast_tanh(mp[idx] * inv);
    const float* vp = g_v2 + p * 2048;
    for (int idx = tid; idx < 2048; idx += 256) sv[idx] = vp[idx];
    __syncthreads();

    const int w = tid >> 5, lane = tid & 31;
#pragma unroll
    for (int i = 0; i < 8; i++) {
        int r = w * 8 + i;
        float* row = sl + r * 128;
        float m = fmaxf(fmaxf(row[lane], row[lane + 32]), fmaxf(row[lane + 64], row[lane + 96]));
#pragma unroll
        for (int off = 16; off; off >>= 1) m = fmaxf(m, __shfl_xor_sync(0xffffffffu, m, off));
        float s = 0.f;
#pragma unroll
        for (int t = 0; t < 4; t++) {
            int cc = lane + t * 32;
            float e = __expf(row[cc] - m);
            row[cc] = e; s += e;
        }
#pragma unroll
        for (int off = 16; off; off >>= 1) s += __shfl_xor_sync(0xffffffffu, s, off);
        float is = 1.f / s;
#pragma unroll
        for (int t = 0; t < 4; t++) row[lane + t * 32] *= is;
    }
    __syncthreads();

    const int r = tid >> 2, d0 = (tid & 3) << 2;
    float a0 = 0.f, a1 = 0.f, a2 = 0.f, a3 = 0.f;
#pragma unroll 4
    for (int cc = 0; cc < 128; cc++) {
        float wgt = sl[r * 128 + cc];
        float4 v = *(const float4*)(sv + cc * 16 + d0);
        a0 += wgt * v.x; a1 += wgt * v.y; a2 += wgt * v.z; a3 += wgt * v.w;
    }
    const int b = p >> 4, h = p & 15;
    float* out = g_attn1 + (b * 128 + rh * 64 + r) * 256 + h * 16 + d0;
    *(float4*)out = make_float4(a0, a1, a2, a3);
}

// ---------------- K5b: h2 attention (softmax over r), 2 blocks per plane ----------------
#define SM_AT2 (14848 * 4)
__global__ void k_attn2() {
    extern __shared__ float smb[];
    float* sl   = smb;              // [128 r][64 c]
    float* sv   = smb + 8192;       // v1 plane [128 r][16 d]
    float* pr   = smb + 10240;      // [4 seg][64 c][16 d]
    float* redm = smb + 14336;      // [4 seg][64 c]
    float* reds = smb + 14592;      // [4 seg][64 c]
    const int blk = blockIdx.x;     // 256
    const int p = blk >> 1, ch = blk & 1;
    const int tid = threadIdx.x;    // 256
    const float inv = g_stats[1];
    const float* mp = g_ms2 + p * 16384 + ch * 64;
    for (int idx = tid; idx < 8192; idx += 256)
        sl[idx] = 10.f * fast_tanh(mp[(idx >> 6) * 128 + (idx & 63)] * inv);
    const float* vp = g_v1 + p * 2048;
    for (int idx = tid; idx < 2048; idx += 256) sv[idx] = vp[idx];
    __syncthreads();

    const int c = tid & 63, seg = tid >> 6;   // seg owns rows [seg*32, seg*32+32)
    float m = -1e30f;
#pragma unroll 4
    for (int i = 0; i < 32; i++) m = fmaxf(m, sl[(seg * 32 + i) * 64 + c]);
    redm[seg * 64 + c] = m;
    __syncthreads();
    m = fmaxf(fmaxf(redm[c], redm[64 + c]), fmaxf(redm[128 + c], redm[192 + c]));
    float s = 0.f;
#pragma unroll 4
    for (int i = 0; i < 32; i++) {
        int rr = seg * 32 + i;
        float e = __expf(sl[rr * 64 + c] - m);
        sl[rr * 64 + c] = e; s += e;
    }
    reds[seg * 64 + c] = s;

    float acc[16];
#pragma unroll
    for (int j = 0; j < 16; j++) acc[j] = 0.f;
#pragma unroll 2
    for (int i = 0; i < 32; i++) {
        int rr = seg * 32 + i;
        float wgt = sl[rr * 64 + c];
        const float4* v = (const float4*)(sv + rr * 16);
        float4 v0 = v[0], v1 = v[1], v2 = v[2], v3 = v[3];
        acc[0] += wgt * v0.x; acc[1] += wgt * v0.y; acc[2] += wgt * v0.z; acc[3] += wgt * v0.w;
        acc[4] += wgt * v1.x; acc[5] += wgt * v1.y; acc[6] += wgt * v1.z; acc[7] += wgt * v1.w;
        acc[8] += wgt * v2.x; acc[9] += wgt * v2.y; acc[10] += wgt * v2.z; acc[11] += wgt * v2.w;
        acc[12] += wgt * v3.x; acc[13] += wgt * v3.y; acc[14] += wgt * v3.z; acc[15] += wgt * v3.w;
    }
    float* prp = pr + (seg * 64 + c) * 16;
#pragma unroll
    for (int j = 0; j < 4; j++)
        *(float4*)(prp + j * 4) = make_float4(acc[j * 4], acc[j * 4 + 1], acc[j * 4 + 2], acc[j * 4 + 3]);
    __syncthreads();

    const int b = p >> 4, h = p & 15;
    for (int o = tid; o < 1024; o += 256) {
        int cc = o >> 4, d = o & 15;
        float v = pr[(cc) * 16 + d] + pr[(64 + cc) * 16 + d]
                + pr[(128 + cc) * 16 + d] + pr[(192 + cc) * 16 + d];
        float stot = reds[cc] + reds[64 + cc] + reds[128 + cc] + reds[192 + cc];
        g_attn2[(b * 128 + ch * 64 + cc) * 256 + h * 16 + d] = v / stot;
    }
}

// ---------------- K6: output projections ----------------
#define SM_OUT ((32 * 260 + 256 * 64) * 4)
__global__ void k_out(const float* __restrict__ o1w, const float* __restrict__ o2w,
                      float* __restrict__ out) {
    extern __shared__ float smo[];
    float* sA = smo;
    float* sB = smo + 32 * 260;
    const int m0 = blockIdx.x * 32, n0 = blockIdx.y * 64;
    const bool first = (m0 < 1024);
    const float* A = first ? g_attn1 : g_attn2;
    const float* W = first ? o1w : o2w;
    float* dst = out + (first ? 0 : 262144);
    const int mm = m0 & 1023;
    const int tid = threadIdx.x;

    for (int idx = tid; idx < 2048; idx += 256) {
        int row = idx >> 6, kk = (idx & 63) << 2;
        float4 v = *(const float4*)(A + (mm + row) * 256 + kk);
        *(float4*)(sA + row * 260 + kk) = v;
    }
    for (int idx = tid; idx < 4096; idx += 256) {
        int row = idx >> 4, c4 = (idx & 15) << 2;
        float4 v = *(const float4*)(W + row * 256 + n0 + c4);
        *(float4*)(sB + row * 64 + c4) = v;
    }
    __syncthreads();

    const int r = tid >> 3, cg = tid & 7;
    float acc[8];
#pragma unroll
    for (int j = 0; j < 8; j++) acc[j] = 0.f;
    const float4* sB4 = (const float4*)sB;
#pragma unroll 4
    for (int k = 0; k < 256; k++) {
        float a = sA[r * 260 + k];
        float4 b0 = sB4[k * 16 + cg * 2];
        float4 b1 = sB4[k * 16 + cg * 2 + 1];
        acc[0] += a * b0.x; acc[1] += a * b0.y; acc[2] += a * b0.z; acc[3] += a * b0.w;
        acc[4] += a * b1.x; acc[5] += a * b1.y; acc[6] += a * b1.z; acc[7] += a * b1.w;
    }
    float* o = dst + (mm + r) * 256 + n0 + cg * 8;
    *(float4*)(o) = make_float4(acc[0], acc[1], acc[2], acc[3]);
    *(float4*)(o + 4) = make_float4(acc[4], acc[5], acc[6], acc[7]);
}

// ---------------- launch ----------------
extern "C" void kernel_launch(void* const* d_in, const int* in_sizes, int n_in,
                              void* d_out, int out_size) {
    const float* x1   = (const float*)d_in[0];
    const float* x2   = (const float*)d_in[1];
    const float* cost = (const float*)d_in[2];
    const float* Wqv1 = (const float*)d_in[3];
    const float* lin1 = (const float*)d_in[4];
    const float* lin2 = (const float*)d_in[5];
    const float* o1w  = (const float*)d_in[6];
    const float* o2w  = (const float*)d_in[7];
    float* out = (float*)d_out;

    cudaFuncSetAttribute(k_qkv,   cudaFuncAttributeMaxDynamicSharedMemorySize, SM_QKV);
    cudaFuncSetAttribute(k_mlp,   cudaFuncAttributeMaxDynamicSharedMemorySize, SM_MLP);
    cudaFuncSetAttribute(k_attn1, cudaFuncAttributeMaxDynamicSharedMemorySize, SM_AT1);
    cudaFuncSetAttribute(k_attn2, cudaFuncAttributeMaxDynamicSharedMemorySize, SM_AT2);
    cudaFuncSetAttribute(k_out,   cudaFuncAttributeMaxDynamicSharedMemorySize, SM_OUT);

    // keep k_mlp in the profiler's capture slot (4th launch)
    k_qkv<<<dim3(64, 8), 256, SM_QKV>>>(x1, x2, Wqv1);   // 1
    k_prep<<<64, 256>>>(lin1, lin2);                      // 2
    k_nop<<<1, 32>>>();                                   // 3
    k_mlp<<<1024, 256, SM_MLP>>>(cost);                   // 4  <- profiled
    k_std<<<1, 128>>>();                                  // 5
    k_attn1<<<256, 256, SM_AT1>>>();                      // 6
    k_attn2<<<256, 256, SM_AT2>>>();                      // 7
    k_out<<<dim3(64, 4), 256, SM_OUT>>>(o1w, o2w, out);   // 8

    (void)in_sizes; (void)n_in; (void)out_size;
}

// round 8
// speedup vs baseline: 1.4711x; 1.4711x over previous
#include <cuda_runtime.h>
#include <math.h>
#include <stdint.h>

typedef unsigned long long ull;

// ---------------- scratch (device globals; no allocations allowed) ----------------
__device__ float g_qT  [1024 * 256];      // [b*128+r][e]   e = h*16+d
__device__ float g_kTT [8 * 256 * 128];   // [b][e][c]
__device__ float g_v1  [1024 * 256];      // [b][h][s][d]
__device__ float g_v2  [1024 * 256];      // [b][h][s][d]
__device__ float g_ms1 [2097152];         // [b][h][r][c]
__device__ float g_ms2 [2097152];         // [b][h][r][c]
__device__ float g_attn1[1024 * 256];     // [b*128+r][h*16+d]
__device__ float g_attn2[1024 * 256];     // [b*128+c][h*16+d]
__device__ float g_part[1024 * 4];        // per-block {s1,q1,s2,q2}
__device__ float g_stats[2];              // inv_std1, inv_std2
// frag-packed split weights: per fragment+lane: {bhi0, bhi1, blo0, blo1}
__device__ float4 gW1p[256 * 32];         // frag = nf*4+ks  (nf 0..63, ks 0..3)
__device__ float4 gW2p[256 * 32];         // frag = ks*4+nf  (ks 0..63, nf 0..3)

// ---------------- helpers ----------------
__device__ __forceinline__ float fast_tanh(float x) {
    return 1.f - 2.f / (__expf(2.f * x) + 1.f);
}
__device__ __forceinline__ float tf32f(float x) {
    uint32_t u; asm("cvt.rna.tf32.f32 %0, %1;" : "=r"(u) : "f"(x));
    return __uint_as_float(u);
}
__device__ __forceinline__ void mma_tf32(float* c,
                                         uint32_t a0, uint32_t a1, uint32_t a2, uint32_t a3,
                                         uint32_t b0, uint32_t b1) {
    asm volatile(
        "mma.sync.aligned.m16n8k8.row.col.f32.tf32.tf32.f32 "
        "{%0,%1,%2,%3}, {%4,%5,%6,%7}, {%8,%9}, {%0,%1,%2,%3};"
        : "+f"(c[0]), "+f"(c[1]), "+f"(c[2]), "+f"(c[3])
        : "r"(a0), "r"(a1), "r"(a2), "r"(a3), "r"(b0), "r"(b1));
}

__global__ void k_nop() {}

// ---------------- K0: pack W1/W2 into per-fragment hi/lo float4s ----------------
__global__ void k_prep(const float* __restrict__ w1, const float* __restrict__ w2) {
    int idx = blockIdx.x * 256 + threadIdx.x;   // 0..16383
    if (idx >= 16384) return;
    int sel  = idx >> 13;
    int f    = idx & 8191;
    int lane = f & 31;
    int frag = f >> 5;            // 0..255
    int g = lane >> 2, tig = lane & 3;
    float b0, b1;
    if (sel == 0) {
        int nf = frag >> 2, ks = frag & 3;
        b0 = w1[(ks * 8 + tig) * 512 + nf * 8 + g];
        b1 = w1[(ks * 8 + tig + 4) * 512 + nf * 8 + g];
    } else {
        int ks = frag >> 2, nf = frag & 3;
        b0 = w2[(ks * 8 + tig) * 32 + nf * 8 + g];
        b1 = w2[(ks * 8 + tig + 4) * 32 + nf * 8 + g];
    }
    float h0 = tf32f(b0), h1 = tf32f(b1);
    float l0 = tf32f(b0 - h0), l1 = tf32f(b1 - h1);
    float4 v = make_float4(h0, h1, l0, l1);
    if (sel == 0) gW1p[frag * 32 + lane] = v;
    else          gW2p[frag * 32 + lane] = v;
}

// ---------------- K1: qkv projection GEMM ----------------
#define SM_QKV ((32 * 260 + 256 * 64) * 4)
__global__ void k_qkv(const float* __restrict__ x1, const float* __restrict__ x2,
                      const float* __restrict__ W) {
    extern __shared__ float smq[];
    float* sA = smq;             // 32 x 260 (padded)
    float* sB = smq + 32 * 260;  // 256 x 64
    const int m0 = blockIdx.x * 32, n0 = blockIdx.y * 64;
    const bool isX1 = (m0 < 1024);
    const float* src = isX1 ? x1 : x2;
    const int mm = m0 & 1023;
    const int b = mm >> 7, s0 = mm & 127;
    const int tid = threadIdx.x;

    for (int idx = tid; idx < 2048; idx += 256) {
        int row = idx >> 6, kk = (idx & 63) << 2;
        float4 v = *(const float4*)(src + (b * 128 + s0 + row) * 256 + kk);
        *(float4*)(sA + row * 260 + kk) = v;
    }
    for (int idx = tid; idx < 4096; idx += 256) {
        int row = idx >> 4, c4 = (idx & 15) << 2;
        float4 v = *(const float4*)(W + row * 512 + n0 + c4);
        *(float4*)(sB + row * 64 + c4) = v;
    }
    __syncthreads();

    const int r = tid >> 3, cg = tid & 7;
    float acc[8];
#pragma unroll
    for (int j = 0; j < 8; j++) acc[j] = 0.f;
    const float4* sB4 = (const float4*)sB;
#pragma unroll 4
    for (int k = 0; k < 256; k++) {
        float a = sA[r * 260 + k];
        float4 b0 = sB4[k * 16 + cg * 2];
        float4 b1 = sB4[k * 16 + cg * 2 + 1];
        acc[0] += a * b0.x; acc[1] += a * b0.y; acc[2] += a * b0.z; acc[3] += a * b0.w;
        acc[4] += a * b1.x; acc[5] += a * b1.y; acc[6] += a * b1.z; acc[7] += a * b1.w;
    }

    const int s = s0 + r;
#pragma unroll
    for (int j = 0; j < 8; j++) {
        int n = n0 + cg * 8 + j;
        float v = acc[j];
        if (n < 256) {
            if (isX1) g_qT[(b * 128 + s) * 256 + n] = v;
            else      g_kTT[(b * 256 + n) * 128 + s] = v;
        } else {
            int h = (n - 256) >> 4, d = n & 15;
            float* dst = isX1 ? g_v1 : g_v2;
            dst[((b * 16 + h) * 128 + s) * 16 + d] = v;
        }
    }
}

// ---------------- K3: tensor-core fused dot + MixedScoreFF MLP ----------------
// grid 1024 = (b,r). 256 threads = 8 warps, warp w owns rows (c) [16w,16w+16).
// tf32x2 split: every product = Ahi*Bhi + Alo*Bhi + Ahi*Blo.
// Independent accumulators break MMA dependency chains.
// smem actually used: 54272 B; PADDED to 81920 B to cap residency at 2 CTA/SM,
// leaving ~64 KB of L1D so the 32 KB active weight chunk (gW1p/gW2p) stays
// L1-resident (R6 regression: 4 CTA/SM left 11 KB L1D -> weight LDGs thrashed
// to L2/DRAM and starved the tensor pipe).
#define SM_MLP 81920
__global__ void __launch_bounds__(256, 2)
k_mlp(const float* __restrict__ cost) {
    extern __shared__ float smf[];
    float* sH = smf;                      // pitch 68
    float* sA = smf + 8704;               // pitch 36
    float* sq = smf + 8704 + 4608;

    const int blk = blockIdx.x;           // b*128 + r
    const int b = blk >> 7;
    const int tid = threadIdx.x;
    const int warp = tid >> 5, lane = tid & 31;
    const int g = lane >> 2, tig = lane & 3;

    // ---- phase 0: q row to smem; compute din; build A (fp32) ----
    sq[tid] = g_qT[(blk << 8) + tid];
    __syncthreads();

    {
        const int c = tid & 127, half = tid >> 7;   // half: h 0..7 vs 8..15
        float cv = cost[blk * 128 + c];
        const float* kb = g_kTT + b * 32768 + c;
#pragma unroll
        for (int hh = 0; hh < 8; hh++) {
            int h = half * 8 + hh;
            float a = 0.f;
#pragma unroll
            for (int d = 0; d < 16; d++)
                a += sq[h * 16 + d] * kb[(h * 16 + d) * 128];
            sA[c * 36 + 2 * h] = a * 0.25f;
            sA[c * 36 + 2 * h + 1] = cv;
        }
    }
    __syncthreads();

    // ---- load A fragments, split hi/lo in registers ----
    const int arow0 = warp * 16 + g, arow1 = arow0 + 8;
    uint32_t Ahi[4][4], Alo[4][4];
#pragma unroll
    for (int ks = 0; ks < 4; ks++) {
        float a0 = sA[arow0 * 36 + ks * 8 + tig];
        float a1 = sA[arow1 * 36 + ks * 8 + tig];
        float a2 = sA[arow0 * 36 + ks * 8 + tig + 4];
        float a3 = sA[arow1 * 36 + ks * 8 + tig + 4];
        float h0 = tf32f(a0), h1 = tf32f(a1), h2 = tf32f(a2), h3 = tf32f(a3);
        Ahi[ks][0] = __float_as_uint(h0); Alo[ks][0] = __float_as_uint(tf32f(a0 - h0));
        Ahi[ks][1] = __float_as_uint(h1); Alo[ks][1] = __float_as_uint(tf32f(a1 - h1));
        Ahi[ks][2] = __float_as_uint(h2); Alo[ks][2] = __float_as_uint(tf32f(a2 - h2));
        Ahi[ks][3] = __float_as_uint(h3); Alo[ks][3] = __float_as_uint(tf32f(a3 - h3));
    }

    float OUThh[4][4], OUTc[4][4];
#pragma unroll
    for (int i = 0; i < 4; i++)
#pragma unroll
        for (int j = 0; j < 4; j++) { OUThh[i][j] = 0.f; OUTc[i][j] = 0.f; }

    // ---- 8 chunks of 64 hidden units ----
    for (int chunk = 0; chunk < 8; chunk++) {
        // layer 1: H[16x64] for this warp's rows; 3 independent chains of depth 4
#pragma unroll
        for (int nfp = 0; nfp < 8; nfp++) {
            float hh[4] = {0.f, 0.f, 0.f, 0.f};
            float lh[4] = {0.f, 0.f, 0.f, 0.f};
            float hl[4] = {0.f, 0.f, 0.f, 0.f};
#pragma unroll
            for (int ks = 0; ks < 4; ks++) {
                float4 bw = gW1p[(((chunk * 8 + nfp) * 4 + ks) << 5) + lane];
                uint32_t bh0 = __float_as_uint(bw.x), bh1 = __float_as_uint(bw.y);
                uint32_t bl0 = __float_as_uint(bw.z), bl1 = __float_as_uint(bw.w);
                mma_tf32(hh, Ahi[ks][0], Ahi[ks][1], Ahi[ks][2], Ahi[ks][3], bh0, bh1);
                mma_tf32(lh, Alo[ks][0], Alo[ks][1], Alo[ks][2], Alo[ks][3], bh0, bh1);
                mma_tf32(hl, Ahi[ks][0], Ahi[ks][1], Ahi[ks][2], Ahi[ks][3], bl0, bl1);
            }
            float h0 = fmaxf(hh[0] + lh[0] + hl[0], 0.f);
            float h1 = fmaxf(hh[1] + lh[1] + hl[1], 0.f);
            float h2 = fmaxf(hh[2] + lh[2] + hl[2], 0.f);
            float h3 = fmaxf(hh[3] + lh[3] + hl[3], 0.f);
            int col = nfp * 8 + 2 * tig;
            sH[arow0 * 68 + col]     = h0;
            sH[arow0 * 68 + col + 1] = h1;
            sH[arow1 * 68 + col]     = h2;
            sH[arow1 * 68 + col + 1] = h3;
        }
        __syncwarp();
        // layer 2: OUT[16x32] += H[16x64] @ W2[64x32]; split H in registers
#pragma unroll
        for (int ksp = 0; ksp < 8; ksp++) {
            float f0 = sH[arow0 * 68 + ksp * 8 + tig];
            float f1 = sH[arow1 * 68 + ksp * 8 + tig];
            float f2 = sH[arow0 * 68 + ksp * 8 + tig + 4];
            float f3 = sH[arow1 * 68 + ksp * 8 + tig + 4];
            float t0 = tf32f(f0), t1 = tf32f(f1), t2 = tf32f(f2), t3 = tf32f(f3);
            uint32_t ah0 = __float_as_uint(t0), ah1 = __float_as_uint(t1);
            uint32_t ah2 = __float_as_uint(t2), ah3 = __float_as_uint(t3);
            uint32_t al0 = __float_as_uint(tf32f(f0 - t0)), al1 = __float_as_uint(tf32f(f1 - t1));
            uint32_t al2 = __float_as_uint(tf32f(f2 - t2)), al3 = __float_as_uint(tf32f(f3 - t3));
#pragma unroll
            for (int nf = 0; nf < 4; nf++) {
                float4 bw = gW2p[(((chunk * 8 + ksp) * 4 + nf) << 5) + lane];
                uint32_t bh0 = __float_as_uint(bw.x), bh1 = __float_as_uint(bw.y);
                uint32_t bl0 = __float_as_uint(bw.z), bl1 = __float_as_uint(bw.w);
                mma_tf32(OUThh[nf], ah0, ah1, ah2, ah3, bh0, bh1);
                mma_tf32(OUTc[nf],  al0, al1, al2, al3, bh0, bh1);
                mma_tf32(OUTc[nf],  ah0, ah1, ah2, ah3, bl0, bl1);
            }
        }
        __syncwarp();
    }

    // ---- write OUT to smem (reuse sH as [128][33]) then coalesced global write ----
    float* sO = sH;
    __syncthreads();   // everyone done with H before repurposing
#pragma unroll
    for (int nf = 0; nf < 4; nf++) {
        int col = nf * 8 + 2 * tig;
        sO[arow0 * 33 + col]     = OUThh[nf][0] + OUTc[nf][0];
        sO[arow0 * 33 + col + 1] = OUThh[nf][1] + OUTc[nf][1];
        sO[arow1 * 33 + col]     = OUThh[nf][2] + OUTc[nf][2];
        sO[arow1 * 33 + col + 1] = OUThh[nf][3] + OUTc[nf][3];
    }
    __syncthreads();

    const int r = blk & 127;
    float s1 = 0.f, q1 = 0.f, s2 = 0.f, q2 = 0.f;
    for (int i = tid; i < 2048; i += 256) {
        int h = i >> 7, cc = i & 127;
        float m1 = sO[cc * 33 + 2 * h];
        float m2 = sO[cc * 33 + 2 * h + 1];
        g_ms1[((b * 16 + h) * 128 + r) * 128 + cc] = m1;
        g_ms2[((b * 16 + h) * 128 + r) * 128 + cc] = m2;
        s1 += m1; q1 += m1 * m1; s2 += m2; q2 += m2 * m2;
    }

    float v[4] = {s1, q1, s2, q2};
#pragma unroll
    for (int i = 0; i < 4; i++)
        for (int off = 16; off; off >>= 1) v[i] += __shfl_xor_sync(0xffffffffu, v[i], off);
    __shared__ float red[4][8];
    if (lane == 0) { red[0][warp] = v[0]; red[1][warp] = v[1]; red[2][warp] = v[2]; red[3][warp] = v[3]; }
    __syncthreads();
    if (tid == 0) {
#pragma unroll
        for (int i = 0; i < 4; i++) {
            float s = 0.f;
#pragma unroll
            for (int j = 0; j < 8; j++) s += red[i][j];
            g_part[blk * 4 + i] = s;
        }
    }
}

// ---------------- K4: std reduction (ddof=1) ----------------
__global__ void k_std() {
    __shared__ double sh[4][128];
    const int tid = threadIdx.x;  // 128
    double a0 = 0, a1 = 0, a2 = 0, a3 = 0;
    for (int i = tid; i < 1024; i += 128) {
        const float* p = g_part + i * 4;
        a0 += p[0]; a1 += p[1]; a2 += p[2]; a3 += p[3];
    }
    sh[0][tid] = a0; sh[1][tid] = a1; sh[2][tid] = a2; sh[3][tid] = a3;
    __syncthreads();
    for (int o = 64; o; o >>= 1) {
        if (tid < o) {
#pragma unroll
            for (int i = 0; i < 4; i++) sh[i][tid] += sh[i][tid + o];
        }
        __syncthreads();
    }
    if (tid == 0) {
        const double N = 2097152.0;
        double v1 = (sh[1][0] - sh[0][0] * sh[0][0] / N) / (N - 1.0);
        double v2 = (sh[3][0] - sh[2][0] * sh[2][0] / N) / (N - 1.0);
        g_stats[0] = (float)(1.0 / sqrt(v1));
        g_stats[1] = (float)(1.0 / sqrt(v2));
    }
}

// ---------------- K5a: h1 attention (softmax over c), 2 blocks per plane ----------------
#define SM_AT1 ((64 * 128 + 128 * 16) * 4)
__global__ void k_attn1() {
    extern __shared__ float sma[];
    float* sl = sma;            // [64 r][128 c]
    float* sv = sma + 8192;     // v2 plane [128 c][16 d]
    const int blk = blockIdx.x;      // 256
    const int p = blk >> 1, rh = blk & 1;
    const int tid = threadIdx.x;     // 256
    const float inv = g_stats[0];
    const float* mp = g_ms1 + p * 16384 + rh * 8192;
    for (int idx = tid; idx < 8192; idx += 256) sl[idx] = 10.f * fast_tanh(mp[idx] * inv);
    const float* vp = g_v2 + p * 2048;
    for (int idx = tid; idx < 2048; idx += 256) sv[idx] = vp[idx];
    __syncthreads();

    const int w = tid >> 5, lane = tid & 31;
#pragma unroll
    for (int i = 0; i < 8; i++) {
        int r = w * 8 + i;
        float* row = sl + r * 128;
        float m = fmaxf(fmaxf(row[lane], row[lane + 32]), fmaxf(row[lane + 64], row[lane + 96]));
#pragma unroll
        for (int off = 16; off; off >>= 1) m = fmaxf(m, __shfl_xor_sync(0xffffffffu, m, off));
        float s = 0.f;
#pragma unroll
        for (int t = 0; t < 4; t++) {
            int cc = lane + t * 32;
            float e = __expf(row[cc] - m);
            row[cc] = e; s += e;
        }
#pragma unroll
        for (int off = 16; off; off >>= 1) s += __shfl_xor_sync(0xffffffffu, s, off);
        float is = 1.f / s;
#pragma unroll
        for (int t = 0; t < 4; t++) row[lane + t * 32] *= is;
    }
    __syncthreads();

    const int r = tid >> 2, d0 = (tid & 3) << 2;
    float a0 = 0.f, a1 = 0.f, a2 = 0.f, a3 = 0.f;
#pragma unroll 4
    for (int cc = 0; cc < 128; cc++) {
        float wgt = sl[r * 128 + cc];
        float4 v = *(const float4*)(sv + cc * 16 + d0);
        a0 += wgt * v.x; a1 += wgt * v.y; a2 += wgt * v.z; a3 += wgt * v.w;
    }
    const int b = p >> 4, h = p & 15;
    float* out = g_attn1 + (b * 128 + rh * 64 + r) * 256 + h * 16 + d0;
    *(float4*)out = make_float4(a0, a1, a2, a3);
}

// ---------------- K5b: h2 attention (softmax over r), 2 blocks per plane ----------------
#define SM_AT2 (14848 * 4)
__global__ void k_attn2() {
    extern __shared__ float smb[];
    float* sl   = smb;              // [128 r][64 c]
    float* sv   = smb + 8192;       // v1 plane [128 r][16 d]
    float* pr   = smb + 10240;      // [4 seg][64 c][16 d]
    float* redm = smb + 14336;      // [4 seg][64 c]
    float* reds = smb + 14592;      // [4 seg][64 c]
    const int blk = blockIdx.x;     // 256
    const int p = blk >> 1, ch = blk & 1;
    const int tid = threadIdx.x;    // 256
    const float inv = g_stats[1];
    const float* mp = g_ms2 + p * 16384 + ch * 64;
    for (int idx = tid; idx < 8192; idx += 256)
        sl[idx] = 10.f * fast_tanh(mp[(idx >> 6) * 128 + (idx & 63)] * inv);
    const float* vp = g_v1 + p * 2048;
    for (int idx = tid; idx < 2048; idx += 256) sv[idx] = vp[idx];
    __syncthreads();

    const int c = tid & 63, seg = tid >> 6;   // seg owns rows [seg*32, seg*32+32)
    float m = -1e30f;
#pragma unroll 4
    for (int i = 0; i < 32; i++) m = fmaxf(m, sl[(seg * 32 + i) * 64 + c]);
    redm[seg * 64 + c] = m;
    __syncthreads();
    m = fmaxf(fmaxf(redm[c], redm[64 + c]), fmaxf(redm[128 + c], redm[192 + c]));
    float s = 0.f;
#pragma unroll 4
    for (int i = 0; i < 32; i++) {
        int rr = seg * 32 + i;
        float e = __expf(sl[rr * 64 + c] - m);
        sl[rr * 64 + c] = e; s += e;
    }
    reds[seg * 64 + c] = s;

    float acc[16];
#pragma unroll
    for (int j = 0; j < 16; j++) acc[j] = 0.f;
#pragma unroll 2
    for (int i = 0; i < 32; i++) {
        int rr = seg * 32 + i;
        float wgt = sl[rr * 64 + c];
        const float4* v = (const float4*)(sv + rr * 16);
        float4 v0 = v[0], v1 = v[1], v2 = v[2], v3 = v[3];
        acc[0] += wgt * v0.x; acc[1] += wgt * v0.y; acc[2] += wgt * v0.z; acc[3] += wgt * v0.w;
        acc[4] += wgt * v1.x; acc[5] += wgt * v1.y; acc[6] += wgt * v1.z; acc[7] += wgt * v1.w;
        acc[8] += wgt * v2.x; acc[9] += wgt * v2.y; acc[10] += wgt * v2.z; acc[11] += wgt * v2.w;
        acc[12] += wgt * v3.x; acc[13] += wgt * v3.y; acc[14] += wgt * v3.z; acc[15] += wgt * v3.w;
    }
    float* prp = pr + (seg * 64 + c) * 16;
#pragma unroll
    for (int j = 0; j < 4; j++)
        *(float4*)(prp + j * 4) = make_float4(acc[j * 4], acc[j * 4 + 1], acc[j * 4 + 2], acc[j * 4 + 3]);
    __syncthreads();

    const int b = p >> 4, h = p & 15;
    for (int o = tid; o < 1024; o += 256) {
        int cc = o >> 4, d = o & 15;
        float v = pr[(cc) * 16 + d] + pr[(64 + cc) * 16 + d]
                + pr[(128 + cc) * 16 + d] + pr[(192 + cc) * 16 + d];
        float stot = reds[cc] + reds[64 + cc] + reds[128 + cc] + reds[192 + cc];
        g_attn2[(b * 128 + ch * 64 + cc) * 256 + h * 16 + d] = v / stot;
    }
}

// ---------------- K6: output projections ----------------
#define SM_OUT ((32 * 260 + 256 * 64) * 4)
__global__ void k_out(const float* __restrict__ o1w, const float* __restrict__ o2w,
                      float* __restrict__ out) {
    extern __shared__ float smo[];
    float* sA = smo;
    float* sB = smo + 32 * 260;
    const int m0 = blockIdx.x * 32, n0 = blockIdx.y * 64;
    const bool first = (m0 < 1024);
    const float* A = first ? g_attn1 : g_attn2;
    const float* W = first ? o1w : o2w;
    float* dst = out + (first ? 0 : 262144);
    const int mm = m0 & 1023;
    const int tid = threadIdx.x;

    for (int idx = tid; idx < 2048; idx += 256) {
        int row = idx >> 6, kk = (idx & 63) << 2;
        float4 v = *(const float4*)(A + (mm + row) * 256 + kk);
        *(float4*)(sA + row * 260 + kk) = v;
    }
    for (int idx = tid; idx < 4096; idx += 256) {
        int row = idx >> 4, c4 = (idx & 15) << 2;
        float4 v = *(const float4*)(W + row * 256 + n0 + c4);
        *(float4*)(sB + row * 64 + c4) = v;
    }
    __syncthreads();

    const int r = tid >> 3, cg = tid & 7;
    float acc[8];
#pragma unroll
    for (int j = 0; j < 8; j++) acc[j] = 0.f;
    const float4* sB4 = (const float4*)sB;
#pragma unroll 4
    for (int k = 0; k < 256; k++) {
        float a = sA[r * 260 + k];
        float4 b0 = sB4[k * 16 + cg * 2];
        float4 b1 = sB4[k * 16 + cg * 2 + 1];
        acc[0] += a * b0.x; acc[1] += a * b0.y; acc[2] += a * b0.z; acc[3] += a * b0.w;
        acc[4] += a * b1.x; acc[5] += a * b1.y; acc[6] += a * b1.z; acc[7] += a * b1.w;
    }
    float* o = dst + (mm + r) * 256 + n0 + cg * 8;
    *(float4*)(o) = make_float4(acc[0], acc[1], acc[2], acc[3]);
    *(float4*)(o + 4) = make_float4(acc[4], acc[5], acc[6], acc[7]);
}

// ---------------- launch ----------------
extern "C" void kernel_launch(void* const* d_in, const int* in_sizes, int n_in,
                              void* d_out, int out_size) {
    const float* x1   = (const float*)d_in[0];
    const float* x2   = (const float*)d_in[1];
    const float* cost = (const float*)d_in[2];
    const float* Wqv1 = (const float*)d_in[3];
    const float* lin1 = (const float*)d_in[4];
    const float* lin2 = (const float*)d_in[5];
    const float* o1w  = (const float*)d_in[6];
    const float* o2w  = (const float*)d_in[7];
    float* out = (float*)d_out;

    cudaFuncSetAttribute(k_qkv,   cudaFuncAttributeMaxDynamicSharedMemorySize, SM_QKV);
    cudaFuncSetAttribute(k_mlp,   cudaFuncAttributeMaxDynamicSharedMemorySize, SM_MLP);
    cudaFuncSetAttribute(k_attn1, cudaFuncAttributeMaxDynamicSharedMemorySize, SM_AT1);
    cudaFuncSetAttribute(k_attn2, cudaFuncAttributeMaxDynamicSharedMemorySize, SM_AT2);
    cudaFuncSetAttribute(k_out,   cudaFuncAttributeMaxDynamicSharedMemorySize, SM_OUT);

    // keep k_mlp in the profiler's capture slot (4th launch)
    k_qkv<<<dim3(64, 8), 256, SM_QKV>>>(x1, x2, Wqv1);   // 1
    k_prep<<<64, 256>>>(lin1, lin2);                      // 2
    k_nop<<<1, 32>>>();                                   // 3
    k_mlp<<<1024, 256, SM_MLP>>>(cost);                   // 4  <- profiled
    k_std<<<1, 128>>>();                                  // 5
    k_attn1<<<256, 256, SM_AT1>>>();                      // 6
    k_attn2<<<256, 256, SM_AT2>>>();                      // 7
    k_out<<<dim3(64, 4), 256, SM_OUT>>>(o1w, o2w, out);   // 8

    (void)in_sizes; (void)n_in; (void)out_size;
}